// round 7
// baseline (speedup 1.0000x reference)
#include <cuda_runtime.h>

#define BB   4
#define HH   256
#define WW   256
#define CC   64
#define CIN  3
#define OFFC 18
#define OFFP 20
#define NP   16

// Scratch (allocation-free)
__device__ float4 g_feat[NP * BB * HH * WW];       // NC4HW4 features
__device__ float  g_off [BB * HH * WW * OFFC];     // NHWC offsets
__device__ float  g_cwT [CIN * 9 * CC];
__device__ float  g_owT [CC * 9 * OFFP];
__device__ float  g_dwT [9 * CC * CC];             // [k][c][o]

typedef unsigned long long ull;

__device__ __forceinline__ ull pack2(float lo, float hi) {
    ull r; asm("mov.b64 %0, {%1,%2};" : "=l"(r) : "f"(lo), "f"(hi)); return r;
}
__device__ __forceinline__ float2 unpack2(ull v) {
    float2 r; asm("mov.b64 {%0,%1}, %2;" : "=f"(r.x), "=f"(r.y) : "l"(v)); return r;
}
#define FMA2(a, x, y) asm("fma.rn.f32x2 %0, %1, %2, %0;" : "+l"(a) : "l"(x), "l"(y))
#define MUL2(a, x, y) asm("mul.rn.f32x2 %0, %1, %2;" : "=l"(a) : "l"(x), "l"(y))

// ---------------------------------------------------------------------------
__global__ void prep_kernel(const float* __restrict__ cw,
                            const float* __restrict__ ow,
                            const float* __restrict__ dw) {
    int t = blockIdx.x * blockDim.x + threadIdx.x;
    int nt = gridDim.x * blockDim.x;
    for (int idx = t; idx < CIN * 9 * CC; idx += nt) {
        int o = idx % CC, r = idx / CC;
        g_cwT[idx] = cw[o * (CIN * 9) + r];
    }
    for (int idx = t; idx < CC * 9 * OFFP; idx += nt) {
        int oc = idx % OFFP, ct = idx / OFFP;
        g_owT[idx] = (oc < OFFC) ? ow[oc * (CC * 9) + ct] : 0.0f;
    }
    for (int idx = t; idx < 9 * CC * CC; idx += nt) {
        int o = idx % CC, c = (idx / CC) % CC, k = idx / (CC * CC);
        g_dwT[idx] = dw[(o * CC + c) * 9 + k];
    }
}

// ---------------------------------------------------------------------------
// Kernel 1: x NCHW -> feat NC4HW4, 3x3 conv pad 1
// ---------------------------------------------------------------------------
__global__ void __launch_bounds__(256) conv_in_kernel(const float* __restrict__ x,
                                                      const float* __restrict__ cb) {
    __shared__ __align__(16) float sw[CIN * 9 * CC];
    __shared__ float sb[CC];
    for (int idx = threadIdx.x; idx < CIN * 9 * CC; idx += 256) sw[idx] = g_cwT[idx];
    if (threadIdx.x < CC) sb[threadIdx.x] = cb[threadIdx.x];
    __syncthreads();

    const int b = blockIdx.x / HH, h = blockIdx.x % HH, w = threadIdx.x;

    ull acc[32];
    #pragma unroll
    for (int q = 0; q < 32; q++) acc[q] = pack2(sb[2 * q], sb[2 * q + 1]);

    #pragma unroll 1
    for (int ci = 0; ci < CIN; ci++) {
        #pragma unroll
        for (int i = 0; i < 3; i++) {
            int y = h - 1 + i;
            bool yv = ((unsigned)y < HH);
            #pragma unroll
            for (int j = 0; j < 3; j++) {
                int xx = w - 1 + j;
                float v = (yv && (unsigned)xx < WW) ? x[((b * CIN + ci) * HH + y) * WW + xx] : 0.0f;
                ull s2 = pack2(v, v);
                const ulonglong2* wp = (const ulonglong2*)&sw[(ci * 9 + i * 3 + j) * CC];
                #pragma unroll
                for (int q = 0; q < 16; q++) {
                    ulonglong2 ww = wp[q];
                    FMA2(acc[2 * q], s2, ww.x);
                    FMA2(acc[2 * q + 1], s2, ww.y);
                }
            }
        }
    }

    const int ppix = h * WW + w;
    #pragma unroll
    for (int q4 = 0; q4 < NP; q4++) {
        float2 lo = unpack2(acc[2 * q4]);
        float2 hi = unpack2(acc[2 * q4 + 1]);
        g_feat[(q4 * BB + b) * HH * WW + ppix] = make_float4(lo.x, lo.y, hi.x, hi.y);
    }
}

// ---------------------------------------------------------------------------
// Kernel 2: feat NC4HW4 -> offsets NHWC(18), 2 rows per block
// ---------------------------------------------------------------------------
__global__ void __launch_bounds__(256) conv_off_kernel(const float* __restrict__ ob) {
    __shared__ __align__(16) float sw[CC * 9 * OFFP];
    for (int idx = threadIdx.x; idx < CC * 9 * OFFP; idx += 256) sw[idx] = g_owT[idx];
    __syncthreads();

    const int b = blockIdx.x / (HH / 2);
    const int h0 = (blockIdx.x % (HH / 2)) * 2;
    const int w = threadIdx.x;

    ull accA[9], accB[9];
    #pragma unroll
    for (int q = 0; q < 9; q++) {
        ull t = pack2(ob[2 * q], ob[2 * q + 1]);
        accA[q] = t; accB[q] = t;
    }

    #pragma unroll 1
    for (int i = 0; i < 3; i++) {
        int yA = h0 - 1 + i, yB = h0 + i;
        bool yAv = ((unsigned)yA < HH), yBv = ((unsigned)yB < HH);
        #pragma unroll 1
        for (int j = 0; j < 3; j++) {
            int xx = w - 1 + j;
            bool xv = ((unsigned)xx < WW);
            bool vA = yAv && xv, vB = yBv && xv;
            int xc = xv ? xx : 0;
            int iA = (vA ? yA : 0) * WW + xc;
            int iB = (vB ? yB : 0) * WW + xc;
            const int tap = i * 3 + j;
            #pragma unroll 1
            for (int c4 = 0; c4 < NP; c4++) {
                const float4* pc = g_feat + (c4 * BB + b) * HH * WW;
                float4 fa = vA ? pc[iA] : make_float4(0.f, 0.f, 0.f, 0.f);
                float4 fb = vB ? pc[iB] : make_float4(0.f, 0.f, 0.f, 0.f);
                const float fav[4] = {fa.x, fa.y, fa.z, fa.w};
                const float fbv[4] = {fb.x, fb.y, fb.z, fb.w};
                #pragma unroll
                for (int cc = 0; cc < 4; cc++) {
                    ull sa = pack2(fav[cc], fav[cc]);
                    ull sb2 = pack2(fbv[cc], fbv[cc]);
                    const float* wrow = &sw[((c4 * 4 + cc) * 9 + tap) * OFFP];
                    const ulonglong2* wp = (const ulonglong2*)wrow;
                    #pragma unroll
                    for (int q2 = 0; q2 < 4; q2++) {
                        ulonglong2 ww = wp[q2];
                        FMA2(accA[2 * q2], sa, ww.x);
                        FMA2(accA[2 * q2 + 1], sa, ww.y);
                        FMA2(accB[2 * q2], sb2, ww.x);
                        FMA2(accB[2 * q2 + 1], sb2, ww.y);
                    }
                    ull w8 = *(const ull*)(wrow + 16);
                    FMA2(accA[8], sa, w8);
                    FMA2(accB[8], sb2, w8);
                }
            }
        }
    }

    float* opA = &g_off[((b * HH + h0) * WW + w) * OFFC];
    float* opB = opA + WW * OFFC;
    #pragma unroll
    for (int q = 0; q < 9; q++) {
        ((float2*)opA)[q] = unpack2(accA[q]);
        ((float2*)opB)[q] = unpack2(accB[q]);
    }
}

// ---------------------------------------------------------------------------
// Kernel 3: deform conv staged GEMM. 128 threads, 4 warps, warp = 128px x 16o.
// S double-buffered in smem (64KB total). W read per-c via warp-uniform __ldg
// broadcasts (L1-hot). Bilinear combine in f32x2. 3 CTAs/SM.
// ---------------------------------------------------------------------------
__device__ __forceinline__ void tap_coords(int h, int w_img, int kk, float2 o2,
                                           float& w00, float& w01, float& w10, float& w11,
                                           int& i00, int& i01, int& i10, int& i11) {
    const int i = kk / 3, j = kk - 3 * i;
    float sy = (float)(h - 1 + i) + o2.x;
    float sx = (float)(w_img - 1 + j) + o2.y;
    float y0f = floorf(sy), x0f = floorf(sx);
    float dy = sy - y0f, dx = sx - x0f;
    int y0 = (int)y0f, x0 = (int)x0f, y1 = y0 + 1, x1 = x0 + 1;
    bool vy0 = ((unsigned)y0 < HH), vy1 = ((unsigned)y1 < HH);
    bool vx0 = ((unsigned)x0 < WW), vx1 = ((unsigned)x1 < WW);
    w00 = (1.f - dy) * (1.f - dx) * ((vy0 && vx0) ? 1.f : 0.f);
    w01 = (1.f - dy) * dx         * ((vy0 && vx1) ? 1.f : 0.f);
    w10 = dy * (1.f - dx)         * ((vy1 && vx0) ? 1.f : 0.f);
    w11 = dy * dx                 * ((vy1 && vx1) ? 1.f : 0.f);
    int y0c = min(max(y0, 0), HH - 1), y1c = min(max(y1, 0), HH - 1);
    int x0c = min(max(x0, 0), WW - 1), x1c = min(max(x1, 0), WW - 1);
    i00 = y0c * WW + x0c; i01 = y0c * WW + x1c;
    i10 = y1c * WW + x0c; i11 = y1c * WW + x1c;
}

__device__ __forceinline__ void bil_store(float* Sd, int px_g, int cb,
                                          ulonglong2 a, ulonglong2 b2,
                                          ulonglong2 c2, ulonglong2 d2,
                                          ull W00, ull W01, ull W10, ull W11) {
    ull s01, s23;
    MUL2(s01, W00, a.x);
    FMA2(s01, W01, b2.x); FMA2(s01, W10, c2.x); FMA2(s01, W11, d2.x);
    MUL2(s23, W00, a.y);
    FMA2(s23, W01, b2.y); FMA2(s23, W10, c2.y); FMA2(s23, W11, d2.y);
    float2 u01 = unpack2(s01), u23 = unpack2(s23);
    Sd[(cb + 0) * 128 + px_g] = u01.x;
    Sd[(cb + 1) * 128 + px_g] = u01.y;
    Sd[(cb + 2) * 128 + px_g] = u23.x;
    Sd[(cb + 3) * 128 + px_g] = u23.y;
}

__global__ void __launch_bounds__(128, 3) deform_kernel(const float* __restrict__ db,
                                                        float* __restrict__ out) {
    extern __shared__ __align__(16) float smem[];
    float* Sb0 = smem;            // 8192 floats (S[64][128])
    float* Sb1 = smem + 8192;

    const int tid = threadIdx.x;
    const int bi = blockIdx.x;
    const int b = bi >> 9;
    const int rest = bi & 511;
    const int h = rest >> 1;
    const int wbase = (rest & 1) << 7;

    const int px_g = tid;                 // gather pixel (0..127)
    const int w_img = wbase + px_g;

    const int lane = tid & 31;
    const int o_t = tid >> 5;             // 0..3 (16 outputs each)

    const float* offp = g_off + (((b * HH + h) * WW) + w_img) * OFFC;

    // Prologue: gather tap 0 into Sb0
    {
        float2 o2 = __ldg((const float2*)offp);
        float w00, w01, w10, w11; int i00, i01, i10, i11;
        tap_coords(h, w_img, 0, o2, w00, w01, w10, w11, i00, i01, i10, i11);
        ull W00 = pack2(w00, w00), W01 = pack2(w01, w01);
        ull W10 = pack2(w10, w10), W11 = pack2(w11, w11);
        #pragma unroll
        for (int pl = 0; pl < NP; pl++) {
            const ulonglong2* pc = (const ulonglong2*)(g_feat + (pl * BB + b) * HH * WW);
            bil_store(Sb0, px_g, pl * 4, pc[i00], pc[i01], pc[i10], pc[i11],
                      W00, W01, W10, W11);
        }
    }
    __syncthreads();

    ull acc[4][8];
    #pragma unroll
    for (int pp = 0; pp < 4; pp++)
        #pragma unroll
        for (int op = 0; op < 8; op++) acc[pp][op] = 0ull;

    #pragma unroll 1
    for (int k = 0; k < 9; k++) {
        const float* Sb = (k & 1) ? Sb1 : Sb0;
        float* Sd = (k & 1) ? Sb0 : Sb1;
        const int kk = k + 1;
        const bool dog = (kk < 9);

        ull W00 = 0, W01 = 0, W10 = 0, W11 = 0;
        int i00 = 0, i01 = 0, i10 = 0, i11 = 0;
        if (dog) {
            float2 o2 = __ldg((const float2*)(offp + 2 * kk));
            float w00, w01, w10, w11;
            tap_coords(h, w_img, kk, o2, w00, w01, w10, w11, i00, i01, i10, i11);
            W00 = pack2(w00, w00); W01 = pack2(w01, w01);
            W10 = pack2(w10, w10); W11 = pack2(w11, w11);
        }
        // W tap base: warp-uniform broadcast loads
        const ulonglong2* wk = (const ulonglong2*)(g_dwT + k * CC * CC) + o_t * 4;

        #pragma unroll
        for (int p = 0; p < NP; p++) {
            ulonglong2 c00, c01, c10, c11;
            if (dog) {
                const ulonglong2* pc = (const ulonglong2*)(g_feat + (p * BB + b) * HH * WW);
                c00 = pc[i00]; c01 = pc[i01]; c10 = pc[i10]; c11 = pc[i11];
            }

            // GEMM chunk: c = p*4 .. p*4+3
            #pragma unroll
            for (int cc = 0; cc < 4; cc++) {
                const int c = p * 4 + cc;
                float4 sv = *(const float4*)(Sb + c * 128 + lane * 4);
                const ulonglong2* wp = wk + c * 16;
                ulonglong2 wA = __ldg(wp);
                ulonglong2 wB = __ldg(wp + 1);
                ulonglong2 wC = __ldg(wp + 2);
                ulonglong2 wD = __ldg(wp + 3);
                ull s;
                s = pack2(sv.x, sv.x);
                FMA2(acc[0][0], s, wA.x); FMA2(acc[0][1], s, wA.y);
                FMA2(acc[0][2], s, wB.x); FMA2(acc[0][3], s, wB.y);
                FMA2(acc[0][4], s, wC.x); FMA2(acc[0][5], s, wC.y);
                FMA2(acc[0][6], s, wD.x); FMA2(acc[0][7], s, wD.y);
                s = pack2(sv.y, sv.y);
                FMA2(acc[1][0], s, wA.x); FMA2(acc[1][1], s, wA.y);
                FMA2(acc[1][2], s, wB.x); FMA2(acc[1][3], s, wB.y);
                FMA2(acc[1][4], s, wC.x); FMA2(acc[1][5], s, wC.y);
                FMA2(acc[1][6], s, wD.x); FMA2(acc[1][7], s, wD.y);
                s = pack2(sv.z, sv.z);
                FMA2(acc[2][0], s, wA.x); FMA2(acc[2][1], s, wA.y);
                FMA2(acc[2][2], s, wB.x); FMA2(acc[2][3], s, wB.y);
                FMA2(acc[2][4], s, wC.x); FMA2(acc[2][5], s, wC.y);
                FMA2(acc[2][6], s, wD.x); FMA2(acc[2][7], s, wD.y);
                s = pack2(sv.w, sv.w);
                FMA2(acc[3][0], s, wA.x); FMA2(acc[3][1], s, wA.y);
                FMA2(acc[3][2], s, wB.x); FMA2(acc[3][3], s, wB.y);
                FMA2(acc[3][4], s, wC.x); FMA2(acc[3][5], s, wC.y);
                FMA2(acc[3][6], s, wD.x); FMA2(acc[3][7], s, wD.y);
            }

            if (dog)
                bil_store(Sd, px_g, p * 4, c00, c01, c10, c11, W00, W01, W10, W11);
        }
        __syncthreads();
    }

    // Epilogue: add bias, write NCHW
    const float2* db2 = (const float2*)db;
    const int wOff = o_t * 16;
    #pragma unroll
    for (int op = 0; op < 8; op++) {
        float2 bz = db2[o_t * 8 + op];
        const int o = wOff + op * 2;
        #pragma unroll
        for (int pp = 0; pp < 4; pp++) {
            float2 v = unpack2(acc[pp][op]);
            const int base = ((b * CC + o) * HH + h) * WW + wbase + lane * 4 + pp;
            out[base] = v.x + bz.x;
            out[base + HH * WW] = v.y + bz.y;
        }
    }
}

// ---------------------------------------------------------------------------
extern "C" void kernel_launch(void* const* d_in, const int* in_sizes, int n_in,
                              void* d_out, int out_size) {
    const float* x        = (const float*)d_in[0];
    const float* conv_w   = (const float*)d_in[1];
    const float* conv_b   = (const float*)d_in[2];
    const float* offset_w = (const float*)d_in[3];
    const float* offset_b = (const float*)d_in[4];
    const float* deform_w = (const float*)d_in[5];
    const float* deform_b = (const float*)d_in[6];
    float* out = (float*)d_out;

    const int dsm = 16384 * (int)sizeof(float);   // 64KB
    cudaFuncSetAttribute(deform_kernel, cudaFuncAttributeMaxDynamicSharedMemorySize, dsm);

    prep_kernel<<<96, 512>>>(conv_w, offset_w, deform_w);
    conv_in_kernel<<<BB * HH, 256>>>(x, conv_b);
    conv_off_kernel<<<BB * HH / 2, 256>>>(offset_b);
    deform_kernel<<<BB * HH * 2, 128, dsm>>>(deform_b, out);
}

// round 8
// speedup vs baseline: 1.2715x; 1.2715x over previous
#include <cuda_runtime.h>

#define BB   4
#define HH   256
#define WW   256
#define CC   64
#define CIN  3
#define OFFC 18
#define OFFP 20
#define NP   16

// Scratch (allocation-free)
__device__ float4 g_feat[NP * BB * HH * WW];       // NC4HW4 features
__device__ float  g_off [BB * HH * WW * OFFC];     // NHWC offsets
__device__ float  g_cwT [CIN * 9 * CC];
__device__ float  g_owT [CC * 9 * OFFP];
__device__ float  g_dwT [9 * CC * CC];             // [k][c][o]

typedef unsigned long long ull;

__device__ __forceinline__ ull pack2(float lo, float hi) {
    ull r; asm("mov.b64 %0, {%1,%2};" : "=l"(r) : "f"(lo), "f"(hi)); return r;
}
__device__ __forceinline__ float2 unpack2(ull v) {
    float2 r; asm("mov.b64 {%0,%1}, %2;" : "=f"(r.x), "=f"(r.y) : "l"(v)); return r;
}
#define FMA2(a, x, y) asm("fma.rn.f32x2 %0, %1, %2, %0;" : "+l"(a) : "l"(x), "l"(y))
#define MUL2(a, x, y) asm("mul.rn.f32x2 %0, %1, %2;" : "=l"(a) : "l"(x), "l"(y))

// ---------------------------------------------------------------------------
__global__ void prep_kernel(const float* __restrict__ cw,
                            const float* __restrict__ ow,
                            const float* __restrict__ dw) {
    int t = blockIdx.x * blockDim.x + threadIdx.x;
    int nt = gridDim.x * blockDim.x;
    for (int idx = t; idx < CIN * 9 * CC; idx += nt) {
        int o = idx % CC, r = idx / CC;
        g_cwT[idx] = cw[o * (CIN * 9) + r];
    }
    for (int idx = t; idx < CC * 9 * OFFP; idx += nt) {
        int oc = idx % OFFP, ct = idx / OFFP;
        g_owT[idx] = (oc < OFFC) ? ow[oc * (CC * 9) + ct] : 0.0f;
    }
    for (int idx = t; idx < 9 * CC * CC; idx += nt) {
        int o = idx % CC, c = (idx / CC) % CC, k = idx / (CC * CC);
        g_dwT[idx] = dw[(o * CC + c) * 9 + k];
    }
}

// ---------------------------------------------------------------------------
// Kernel 1: x NCHW -> feat NC4HW4, 3x3 conv pad 1
// ---------------------------------------------------------------------------
__global__ void __launch_bounds__(256) conv_in_kernel(const float* __restrict__ x,
                                                      const float* __restrict__ cb) {
    __shared__ __align__(16) float sw[CIN * 9 * CC];
    __shared__ float sb[CC];
    for (int idx = threadIdx.x; idx < CIN * 9 * CC; idx += 256) sw[idx] = g_cwT[idx];
    if (threadIdx.x < CC) sb[threadIdx.x] = cb[threadIdx.x];
    __syncthreads();

    const int b = blockIdx.x / HH, h = blockIdx.x % HH, w = threadIdx.x;

    ull acc[32];
    #pragma unroll
    for (int q = 0; q < 32; q++) acc[q] = pack2(sb[2 * q], sb[2 * q + 1]);

    #pragma unroll 1
    for (int ci = 0; ci < CIN; ci++) {
        #pragma unroll
        for (int i = 0; i < 3; i++) {
            int y = h - 1 + i;
            bool yv = ((unsigned)y < HH);
            #pragma unroll
            for (int j = 0; j < 3; j++) {
                int xx = w - 1 + j;
                float v = (yv && (unsigned)xx < WW) ? x[((b * CIN + ci) * HH + y) * WW + xx] : 0.0f;
                ull s2 = pack2(v, v);
                const ulonglong2* wp = (const ulonglong2*)&sw[(ci * 9 + i * 3 + j) * CC];
                #pragma unroll
                for (int q = 0; q < 16; q++) {
                    ulonglong2 ww = wp[q];
                    FMA2(acc[2 * q], s2, ww.x);
                    FMA2(acc[2 * q + 1], s2, ww.y);
                }
            }
        }
    }

    const int ppix = h * WW + w;
    #pragma unroll
    for (int q4 = 0; q4 < NP; q4++) {
        float2 lo = unpack2(acc[2 * q4]);
        float2 hi = unpack2(acc[2 * q4 + 1]);
        g_feat[(q4 * BB + b) * HH * WW + ppix] = make_float4(lo.x, lo.y, hi.x, hi.y);
    }
}

// ---------------------------------------------------------------------------
// Kernel 2: feat NC4HW4 -> offsets NHWC(18), 2 rows per block
// ---------------------------------------------------------------------------
__global__ void __launch_bounds__(256) conv_off_kernel(const float* __restrict__ ob) {
    __shared__ __align__(16) float sw[CC * 9 * OFFP];
    for (int idx = threadIdx.x; idx < CC * 9 * OFFP; idx += 256) sw[idx] = g_owT[idx];
    __syncthreads();

    const int b = blockIdx.x / (HH / 2);
    const int h0 = (blockIdx.x % (HH / 2)) * 2;
    const int w = threadIdx.x;

    ull accA[9], accB[9];
    #pragma unroll
    for (int q = 0; q < 9; q++) {
        ull t = pack2(ob[2 * q], ob[2 * q + 1]);
        accA[q] = t; accB[q] = t;
    }

    #pragma unroll 1
    for (int i = 0; i < 3; i++) {
        int yA = h0 - 1 + i, yB = h0 + i;
        bool yAv = ((unsigned)yA < HH), yBv = ((unsigned)yB < HH);
        #pragma unroll 1
        for (int j = 0; j < 3; j++) {
            int xx = w - 1 + j;
            bool xv = ((unsigned)xx < WW);
            bool vA = yAv && xv, vB = yBv && xv;
            int xc = xv ? xx : 0;
            int iA = (vA ? yA : 0) * WW + xc;
            int iB = (vB ? yB : 0) * WW + xc;
            const int tap = i * 3 + j;
            #pragma unroll 1
            for (int c4 = 0; c4 < NP; c4++) {
                const float4* pc = g_feat + (c4 * BB + b) * HH * WW;
                float4 fa = vA ? pc[iA] : make_float4(0.f, 0.f, 0.f, 0.f);
                float4 fb = vB ? pc[iB] : make_float4(0.f, 0.f, 0.f, 0.f);
                const float fav[4] = {fa.x, fa.y, fa.z, fa.w};
                const float fbv[4] = {fb.x, fb.y, fb.z, fb.w};
                #pragma unroll
                for (int cc = 0; cc < 4; cc++) {
                    ull sa = pack2(fav[cc], fav[cc]);
                    ull sb2 = pack2(fbv[cc], fbv[cc]);
                    const float* wrow = &sw[((c4 * 4 + cc) * 9 + tap) * OFFP];
                    const ulonglong2* wp = (const ulonglong2*)wrow;
                    #pragma unroll
                    for (int q2 = 0; q2 < 4; q2++) {
                        ulonglong2 ww = wp[q2];
                        FMA2(accA[2 * q2], sa, ww.x);
                        FMA2(accA[2 * q2 + 1], sa, ww.y);
                        FMA2(accB[2 * q2], sb2, ww.x);
                        FMA2(accB[2 * q2 + 1], sb2, ww.y);
                    }
                    ull w8 = *(const ull*)(wrow + 16);
                    FMA2(accA[8], sa, w8);
                    FMA2(accB[8], sb2, w8);
                }
            }
        }
    }

    float* opA = &g_off[((b * HH + h0) * WW + w) * OFFC];
    float* opB = opA + WW * OFFC;
    #pragma unroll
    for (int q = 0; q < 9; q++) {
        ((float2*)opA)[q] = unpack2(accA[q]);
        ((float2*)opB)[q] = unpack2(accB[q]);
    }
}

// ---------------------------------------------------------------------------
// Kernel 3: deform conv staged GEMM, occupancy-first variant.
// 128 threads, 4 warps, warp = 128px x 16o. Single S buffer (32KB) + single
// W tap buffer (16KB) = 48KB smem -> 3-4 CTAs/SM. Per tap:
// sync; load W(k) + gather S(k) (f32x2 bilinear); sync; GEMM(k).
// Inter-CTA overlap hides the serial phases.
// ---------------------------------------------------------------------------
__device__ __forceinline__ void tap_coords(int h, int w_img, int kk, float2 o2,
                                           float& w00, float& w01, float& w10, float& w11,
                                           int& i00, int& i01, int& i10, int& i11) {
    const int i = kk / 3, j = kk - 3 * i;
    float sy = (float)(h - 1 + i) + o2.x;
    float sx = (float)(w_img - 1 + j) + o2.y;
    float y0f = floorf(sy), x0f = floorf(sx);
    float dy = sy - y0f, dx = sx - x0f;
    int y0 = (int)y0f, x0 = (int)x0f, y1 = y0 + 1, x1 = x0 + 1;
    bool vy0 = ((unsigned)y0 < HH), vy1 = ((unsigned)y1 < HH);
    bool vx0 = ((unsigned)x0 < WW), vx1 = ((unsigned)x1 < WW);
    w00 = (1.f - dy) * (1.f - dx) * ((vy0 && vx0) ? 1.f : 0.f);
    w01 = (1.f - dy) * dx         * ((vy0 && vx1) ? 1.f : 0.f);
    w10 = dy * (1.f - dx)         * ((vy1 && vx0) ? 1.f : 0.f);
    w11 = dy * dx                 * ((vy1 && vx1) ? 1.f : 0.f);
    int y0c = min(max(y0, 0), HH - 1), y1c = min(max(y1, 0), HH - 1);
    int x0c = min(max(x0, 0), WW - 1), x1c = min(max(x1, 0), WW - 1);
    i00 = y0c * WW + x0c; i01 = y0c * WW + x1c;
    i10 = y1c * WW + x0c; i11 = y1c * WW + x1c;
}

__device__ __forceinline__ void bil_store(float* Sd, int px_g, int cb,
                                          ulonglong2 a, ulonglong2 b2,
                                          ulonglong2 c2, ulonglong2 d2,
                                          ull W00, ull W01, ull W10, ull W11) {
    ull s01, s23;
    MUL2(s01, W00, a.x);
    FMA2(s01, W01, b2.x); FMA2(s01, W10, c2.x); FMA2(s01, W11, d2.x);
    MUL2(s23, W00, a.y);
    FMA2(s23, W01, b2.y); FMA2(s23, W10, c2.y); FMA2(s23, W11, d2.y);
    float2 u01 = unpack2(s01), u23 = unpack2(s23);
    Sd[(cb + 0) * 128 + px_g] = u01.x;
    Sd[(cb + 1) * 128 + px_g] = u01.y;
    Sd[(cb + 2) * 128 + px_g] = u23.x;
    Sd[(cb + 3) * 128 + px_g] = u23.y;
}

__global__ void __launch_bounds__(128, 3) deform_kernel(const float* __restrict__ db,
                                                        float* __restrict__ out) {
    extern __shared__ __align__(16) float smem[];
    float* Sb = smem;             // 8192 floats (S[64][128], 32KB)
    float* Wb = smem + 8192;      // 4096 floats (W[64][64], 16KB)

    const int tid = threadIdx.x;
    const int bi = blockIdx.x;
    const int b = bi >> 9;
    const int rest = bi & 511;
    const int h = rest >> 1;
    const int wbase = (rest & 1) << 7;

    const int px_g = tid;                 // gather pixel (0..127)
    const int w_img = wbase + px_g;

    const int lane = tid & 31;
    const int o_t = tid >> 5;             // 0..3 (16 outputs each)

    const float* offp = g_off + (((b * HH + h) * WW) + w_img) * OFFC;

    ull acc[4][8];
    #pragma unroll
    for (int pp = 0; pp < 4; pp++)
        #pragma unroll
        for (int op = 0; op < 8; op++) acc[pp][op] = 0ull;

    #pragma unroll 1
    for (int k = 0; k < 9; k++) {
        __syncthreads();   // previous GEMM done reading Sb/Wb

        // load W tap tile: 1024 float4, 8 per thread
        {
            const float4* gWk = (const float4*)(g_dwT + k * CC * CC);
            #pragma unroll
            for (int q = 0; q < 8; q++)
                ((float4*)Wb)[q * 128 + tid] = gWk[q * 128 + tid];
        }
        // gather + bilinear into S
        {
            float2 o2 = __ldg((const float2*)(offp + 2 * k));
            float w00, w01, w10, w11; int i00, i01, i10, i11;
            tap_coords(h, w_img, k, o2, w00, w01, w10, w11, i00, i01, i10, i11);
            ull W00 = pack2(w00, w00), W01 = pack2(w01, w01);
            ull W10 = pack2(w10, w10), W11 = pack2(w11, w11);
            #pragma unroll
            for (int pl = 0; pl < NP; pl++) {
                const ulonglong2* pc = (const ulonglong2*)(g_feat + (pl * BB + b) * HH * WW);
                bil_store(Sb, px_g, pl * 4, pc[i00], pc[i01], pc[i10], pc[i11],
                          W00, W01, W10, W11);
            }
        }
        __syncthreads();

        // GEMM: acc[4px][16o] += S[c][4px] * W[c][16o]
        #pragma unroll 4
        for (int c = 0; c < CC; c++) {
            float4 sv = *(const float4*)(Sb + c * 128 + lane * 4);
            const ulonglong2* wrow = (const ulonglong2*)(Wb + c * 64 + o_t * 16);
            ulonglong2 wA = wrow[0];
            ulonglong2 wB = wrow[1];
            ulonglong2 wC = wrow[2];
            ulonglong2 wD = wrow[3];
            ull s;
            s = pack2(sv.x, sv.x);
            FMA2(acc[0][0], s, wA.x); FMA2(acc[0][1], s, wA.y);
            FMA2(acc[0][2], s, wB.x); FMA2(acc[0][3], s, wB.y);
            FMA2(acc[0][4], s, wC.x); FMA2(acc[0][5], s, wC.y);
            FMA2(acc[0][6], s, wD.x); FMA2(acc[0][7], s, wD.y);
            s = pack2(sv.y, sv.y);
            FMA2(acc[1][0], s, wA.x); FMA2(acc[1][1], s, wA.y);
            FMA2(acc[1][2], s, wB.x); FMA2(acc[1][3], s, wB.y);
            FMA2(acc[1][4], s, wC.x); FMA2(acc[1][5], s, wC.y);
            FMA2(acc[1][6], s, wD.x); FMA2(acc[1][7], s, wD.y);
            s = pack2(sv.z, sv.z);
            FMA2(acc[2][0], s, wA.x); FMA2(acc[2][1], s, wA.y);
            FMA2(acc[2][2], s, wB.x); FMA2(acc[2][3], s, wB.y);
            FMA2(acc[2][4], s, wC.x); FMA2(acc[2][5], s, wC.y);
            FMA2(acc[2][6], s, wD.x); FMA2(acc[2][7], s, wD.y);
            s = pack2(sv.w, sv.w);
            FMA2(acc[3][0], s, wA.x); FMA2(acc[3][1], s, wA.y);
            FMA2(acc[3][2], s, wB.x); FMA2(acc[3][3], s, wB.y);
            FMA2(acc[3][4], s, wC.x); FMA2(acc[3][5], s, wC.y);
            FMA2(acc[3][6], s, wD.x); FMA2(acc[3][7], s, wD.y);
        }
    }

    // Epilogue: add bias, write NCHW
    const float2* db2 = (const float2*)db;
    const int wOff = o_t * 16;
    #pragma unroll
    for (int op = 0; op < 8; op++) {
        float2 bz = db2[o_t * 8 + op];
        const int o = wOff + op * 2;
        #pragma unroll
        for (int pp = 0; pp < 4; pp++) {
            float2 v = unpack2(acc[pp][op]);
            const int base = ((b * CC + o) * HH + h) * WW + wbase + lane * 4 + pp;
            out[base] = v.x + bz.x;
            out[base + HH * WW] = v.y + bz.y;
        }
    }
}

// ---------------------------------------------------------------------------
extern "C" void kernel_launch(void* const* d_in, const int* in_sizes, int n_in,
                              void* d_out, int out_size) {
    const float* x        = (const float*)d_in[0];
    const float* conv_w   = (const float*)d_in[1];
    const float* conv_b   = (const float*)d_in[2];
    const float* offset_w = (const float*)d_in[3];
    const float* offset_b = (const float*)d_in[4];
    const float* deform_w = (const float*)d_in[5];
    const float* deform_b = (const float*)d_in[6];
    float* out = (float*)d_out;

    const int dsm = 12288 * (int)sizeof(float);   // 48KB
    cudaFuncSetAttribute(deform_kernel, cudaFuncAttributeMaxDynamicSharedMemorySize, dsm);

    prep_kernel<<<96, 512>>>(conv_w, offset_w, deform_w);
    conv_in_kernel<<<BB * HH, 256>>>(x, conv_b);
    conv_off_kernel<<<BB * HH / 2, 256>>>(offset_b);
    deform_kernel<<<BB * HH * 2, 128, dsm>>>(deform_b, out);
}